// round 17
// baseline (speedup 1.0000x reference)
#include <cuda_runtime.h>
#include <cuda_fp16.h>

#define D_FEAT 64
#define MAX_NODES 100000
#define NODES_PER_WARP 4

// Scratch (static __device__ arrays -- no allocation).
__device__ int   g_row_ptr[MAX_NODES + 1];
__device__ uint2 g_x16[MAX_NODES * 16];   // fp16 rows: 128B = 16 x uint2 per row

// Fused prep: blocks [0, rp_blocks) build row_ptr from the sorted targets;
// remaining blocks convert x (f32) -> g_x16 (fp16), lane-strided, 8 float4
// in flight per thread (convert was latency-limited at issue 15%).
__global__ __launch_bounds__(256) void prep_kernel(
    const float4* __restrict__ xf4, int n_f4,
    const int* __restrict__ tgt, int n_edges, int n_nodes, int rp_blocks)
{
    const int b = (int)blockIdx.x;
    if (b < rp_blocks) {
        const int e = b * 256 + threadIdx.x;
        if (e >= n_edges) return;
        const int cur  = __ldg(tgt + e);
        const int prev = (e == 0) ? -1 : __ldg(tgt + e - 1);
        for (int v = prev + 1; v <= cur; ++v) g_row_ptr[v] = e;
        if (e == n_edges - 1) {
            for (int v = cur + 1; v <= n_nodes; ++v) g_row_ptr[v] = n_edges;
        }
    } else {
        // 8 float4 per thread, lane-strided (+32) -> coalesced LDG.128, MLP=8.
        const int t0 = (b - rp_blocks) * 256 + threadIdx.x;
        const int base = (t0 >> 5) * 256 + (t0 & 31);  // warp owns 256 float4
        #pragma unroll 8
        for (int k = 0; k < 8; ++k) {
            const int i = base + k * 32;
            if (i < n_f4) {
                const float4 a = __ldg(xf4 + i);
                __half2 h0 = __floats2half2_rn(a.x, a.y);
                __half2 h1 = __floats2half2_rn(a.z, a.w);
                uint2 o;
                o.x = *reinterpret_cast<unsigned int*>(&h0);
                o.y = *reinterpret_cast<unsigned int*>(&h1);
                g_x16[i] = o;
            }
        }
    }
}

__device__ __forceinline__ __half2 h2of(unsigned int u) {
    return *reinterpret_cast<__half2*>(&u);
}
__device__ __forceinline__ unsigned int uof(__half2 h) {
    return *reinterpret_cast<unsigned int*>(&h);
}

// One warp serves 4 consecutive nodes; whole warp per edge on the fp16 table
// (row = 128B = 32 lanes x half2; lane l owns features 2l, 2l+1). Weights
// converted to half2 ONCE per 32-edge batch, shuffled as bits. Each 4-edge
// group accumulates in ONE half2 via HFMA2 (chain depth 4), folded to f32:
// per edge 1 SHFL + 1 IADD + 1 LDG.32 + 1 SHFL + 1 HFMA2 + 1 amortized fold
// = ~6 slots vs 8 for the F2F+FFMA version. Temps per group: 4 offsets +
// 4 words + 4 wh-bits + 1 half2 acc -> ~33 regs (R12's HFMA2 failed at 40
// regs only because the half-warp layout carried double the state).
__global__ __launch_bounds__(128) void mp_gather_kernel(
    const float* __restrict__ ev,   // [n_edges]
    const int*   __restrict__ src,  // [n_edges]
    float*       __restrict__ out,  // [n_nodes, 64]
    int n_nodes)
{
    const int warp = (blockIdx.x * blockDim.x + threadIdx.x) >> 5;
    const int v0   = warp * NODES_PER_WARP;
    if (v0 >= n_nodes) return;
    const int lane  = threadIdx.x & 31;
    const int lane4 = lane << 2;          // byte offset of this lane's half2

    const char* __restrict__ xb = (const char*)g_x16;  // row s at byte s*128
    float2* __restrict__ of2 = (float2*)out;
    const __half2 hzero = __floats2half2_rn(0.f, 0.f);

    #pragma unroll 1
    for (int i = 0; i < NODES_PER_WARP; ++i) {
        const int node = v0 + i;
        if (node >= n_nodes) break;

        const int start = __ldg(&g_row_ptr[node]);
        const int end   = __ldg(&g_row_ptr[node + 1]);

        float ax = 0.f, ay = 0.f;

        for (int base = start; base < end; base += 32) {
            const int cnt = min(32, end - base);
            // Cooperative metadata load: lane l owns edge base+l.
            // s pre-shifted to byte row offset; w pre-converted to half2 bits.
            int          s_l  = 0;
            unsigned int wh_l = 0u;
            if (lane < cnt) {
                s_l = __ldg(src + base + lane) << 7;
                wh_l = uof(__float2half2_rn(__ldg(ev + base + lane)));
            }

            int k = 0;
            // Main path: 4 edges in flight; one half2 acc per group.
            for (; k + 4 <= cnt; k += 4) {
                const int o0 = __shfl_sync(0xffffffffu, s_l, k + 0) + lane4;
                const int o1 = __shfl_sync(0xffffffffu, s_l, k + 1) + lane4;
                const int o2 = __shfl_sync(0xffffffffu, s_l, k + 2) + lane4;
                const int o3 = __shfl_sync(0xffffffffu, s_l, k + 3) + lane4;
                const unsigned int u0 = __ldg((const unsigned int*)(xb + o0));
                const unsigned int u1 = __ldg((const unsigned int*)(xb + o1));
                const unsigned int u2 = __ldg((const unsigned int*)(xb + o2));
                const unsigned int u3 = __ldg((const unsigned int*)(xb + o3));
                const unsigned int b0 = __shfl_sync(0xffffffffu, wh_l, k + 0);
                const unsigned int b1 = __shfl_sync(0xffffffffu, wh_l, k + 1);
                const unsigned int b2 = __shfl_sync(0xffffffffu, wh_l, k + 2);
                const unsigned int b3 = __shfl_sync(0xffffffffu, wh_l, k + 3);
                __half2 acc = hzero;
                acc = __hfma2(h2of(b0), h2of(u0), acc);
                acc = __hfma2(h2of(b1), h2of(u1), acc);
                acc = __hfma2(h2of(b2), h2of(u2), acc);
                acc = __hfma2(h2of(b3), h2of(u3), acc);
                const float2 f = __half22float2(acc);
                ax += f.x;
                ay += f.y;
            }
            // Tail (<= 3 edges): short half2 chain, folded once.
            if (k < cnt) {
                __half2 acc = hzero;
                for (; k < cnt; ++k) {
                    const int          o = __shfl_sync(0xffffffffu, s_l, k) + lane4;
                    const unsigned int b = __shfl_sync(0xffffffffu, wh_l, k);
                    const unsigned int u = __ldg((const unsigned int*)(xb + o));
                    acc = __hfma2(h2of(b), h2of(u), acc);
                }
                const float2 f = __half22float2(acc);
                ax += f.x;
                ay += f.y;
            }
        }

        // Every lane stores its own feature pair: 32 x 8B = 256B coalesced.
        of2[(size_t)node * 32 + lane] = make_float2(ax, ay);
    }
}

extern "C" void kernel_launch(void* const* d_in, const int* in_sizes, int n_in,
                              void* d_out, int out_size) {
    const float* x   = (const float*)d_in[0];
    const float* ev  = (const float*)d_in[1];
    const int*   tgt = (const int*)d_in[2];
    const int*   src = (const int*)d_in[3];
    float* out = (float*)d_out;

    const int n_edges = in_sizes[1];
    const int n_nodes = out_size / D_FEAT;
    const int n_f4    = n_nodes * (D_FEAT / 4);

    const int rp_blocks = (n_edges + 255) / 256;
    const int cv_blocks = (n_f4 + 2047) / 2048;      // 8 float4/thread
    prep_kernel<<<rp_blocks + cv_blocks, 256>>>(
        (const float4*)x, n_f4, tgt, n_edges, n_nodes, rp_blocks);

    const int threads = 128;
    const int warps_needed = (n_nodes + NODES_PER_WARP - 1) / NODES_PER_WARP;
    const int blocks = (warps_needed * 32 + threads - 1) / threads;
    mp_gather_kernel<<<blocks, threads>>>(ev, src, out, n_nodes);
}